// round 3
// baseline (speedup 1.0000x reference)
#include <cuda_runtime.h>

// ---------------- problem constants ----------------
#define BSZ   8
#define NC    128
#define TD    512
#define EDIM  64
#define NE    128
#define NTOK  (BSZ*NC)     // 1024 tokens
#define T2    (2*TD)       // 1024 concat dim

// ---------------- GEMM tiling ----------------
#define BN 128             // n-columns per CTA
#define NT (TD/BN)         // 4 n-tiles
#define KC 64              // k-tile
#define MC 32              // m rows per pass

// ---------------- device scratch (no allocation allowed) ----------------
__device__ int   g_cnt[NE];
__device__ int   g_list[NE][NTOK];          // packed token*2 + slot
__device__ float g_part[4][NTOK][TD];       // [slot*2+stream][token][t]  (8 MB)

// ---------------- kernel 0: zero per-expert counters ----------------
__global__ void zero_cnt_kernel() { g_cnt[threadIdx.x] = 0; }

// ---------------- kernel 1: router (top-2 expert indices per token) -----
// s_e = (x @ projW^T + projb) . centers[e] / ||centers[e]||
// The x_proj L2-normalization is a positive per-token scalar (cannot change
// top-k order) and the reference's token-level mask makes the combine weight
// for each selected expert exactly softmax(p0)+softmax(p1) = 1.0, so only
// the top-2 indices matter.
__global__ __launch_bounds__(256) void router_kernel(
    const float* __restrict__ x_l, const float* __restrict__ x_r,
    const float* __restrict__ centers,
    const float* __restrict__ projW, const float* __restrict__ projb)
{
    __shared__ float xs[T2];
    __shared__ float ps[EDIM];
    __shared__ float ss[NE];
    int tok = blockIdx.x;
    int tid = threadIdx.x;
    const float* xl = x_l + (size_t)tok * TD;
    const float* xr = x_r + (size_t)tok * TD;
    for (int i = tid; i < TD; i += 256) { xs[i] = xl[i]; xs[i + TD] = xr[i]; }
    __syncthreads();

    int warp = tid >> 5, lane = tid & 31;
    // 8 warps x 8 iters cover the 64 projection dims
    for (int it = 0; it < 8; ++it) {
        int j = warp + 8 * it;
        const float* w = projW + (size_t)j * T2;
        float s = 0.f;
        #pragma unroll 4
        for (int k = lane; k < T2; k += 32) s += xs[k] * w[k];
        #pragma unroll
        for (int o = 16; o; o >>= 1) s += __shfl_xor_sync(0xffffffffu, s, o);
        if (lane == 0) ps[j] = s + projb[j];
    }
    __syncthreads();

    if (tid < NE) {
        const float* c = centers + (size_t)tid * EDIM;
        float s = 0.f, n = 0.f;
        #pragma unroll 8
        for (int j = 0; j < EDIM; ++j) { float cv = c[j]; s += ps[j] * cv; n += cv * cv; }
        ss[tid] = s * rsqrtf(fmaxf(n, 1e-24f));
    }
    __syncthreads();

    if (tid == 0) {
        // strict > keeps first-index tie-break, matching jax.lax.top_k
        int e0 = 0; float b0 = ss[0];
        for (int e = 1; e < NE; ++e) if (ss[e] > b0) { b0 = ss[e]; e0 = e; }
        int e1 = (e0 == 0) ? 1 : 0; float b1 = ss[e1];
        for (int e = 0; e < NE; ++e) if (e != e0 && ss[e] > b1) { b1 = ss[e]; e1 = e; }
        int p0 = atomicAdd(&g_cnt[e0], 1);
        g_list[e0][p0] = tok * 2 + 0;
        int p1 = atomicAdd(&g_cnt[e1], 1);
        g_list[e1][p1] = tok * 2 + 1;
    }
}

// ---------------- kernel 2: grouped per-expert GEMM ----------------
// CTA (e, nt): rows = gathered (token,stream) rows of expert e,
// computes out[row][n] = x_row . We[n][:] + be[n] for n in [nt*BN, nt*BN+BN)
// plain-fp32 register tile: 4n x 4m per thread.
__global__ __launch_bounds__(256) void expert_gemm_kernel(
    const float* __restrict__ x_l, const float* __restrict__ x_r,
    const float* __restrict__ eW,  const float* __restrict__ eB)
{
    __shared__ float Wst[KC][BN + 4];   // transposed [k][n], 33.0 KB
    __shared__ float xst[KC][MC + 4];   // transposed [k][m],  9.0 KB

    int e = blockIdx.x, nt = blockIdx.y;
    int cnt = g_cnt[e];
    int rows = 2 * cnt;
    if (rows == 0) return;

    int tid  = threadIdx.x;
    int lane = tid & 31;
    int n0l  = lane * 4;             // 0..124
    int m0   = (tid >> 5) * 4;       // 0..28
    int N0   = nt * BN;
    const float* We = eW + (size_t)e * TD * TD + (size_t)N0 * TD;
    float4 bias = *reinterpret_cast<const float4*>(eB + (size_t)e * TD + N0 + n0l);

    // loader roles
    int wl_n = tid >> 1;             // 0..127
    int wl_k = (tid & 1) * 32;       // 0 / 32
    int xl_m = tid >> 3;             // 0..31
    int xl_k = (tid & 7) * 8;        // 0..56

    for (int mp = 0; mp < rows; mp += MC) {
        // per-thread m metadata
        int tok[4], str[4], slot[4], val[4];
        #pragma unroll
        for (int i = 0; i < 4; ++i) {
            int r = mp + m0 + i;
            val[i] = (r < rows);
            int rr = val[i] ? r : 0;
            int entry = (rr < cnt) ? rr : rr - cnt;
            str[i] = (rr < cnt) ? 0 : 1;
            int packed = g_list[e][entry];
            tok[i]  = packed >> 1;
            slot[i] = packed & 1;
        }
        // loader-side x row pointer
        const float* xsrc = nullptr;
        {
            int lr = mp + xl_m;
            if (lr < rows) {
                int entry = (lr < cnt) ? lr : lr - cnt;
                const float* base = (lr < cnt) ? x_l : x_r;
                xsrc = base + (size_t)(g_list[e][entry] >> 1) * TD;
            }
        }

        float acc[4][4];   // [n][m]
        #pragma unroll
        for (int i = 0; i < 4; ++i)
            #pragma unroll
            for (int j = 0; j < 4; ++j) acc[i][j] = 0.f;

        for (int kt = 0; kt < TD / KC; ++kt) {
            int k0 = kt * KC;
            __syncthreads();
            // W tile: coalesced float4 reads, transposed scatter to smem
            {
                const float* src = We + (size_t)wl_n * TD + k0 + wl_k;
                #pragma unroll
                for (int i = 0; i < 8; ++i) {
                    float4 v = *reinterpret_cast<const float4*>(src + i * 4);
                    int kk = wl_k + i * 4;
                    Wst[kk + 0][wl_n] = v.x;
                    Wst[kk + 1][wl_n] = v.y;
                    Wst[kk + 2][wl_n] = v.z;
                    Wst[kk + 3][wl_n] = v.w;
                }
            }
            // x tile (zero-fill padding rows)
            {
                #pragma unroll
                for (int i = 0; i < 2; ++i) {
                    float4 v = xsrc ? *reinterpret_cast<const float4*>(xsrc + k0 + xl_k + i * 4)
                                    : make_float4(0.f, 0.f, 0.f, 0.f);
                    int kk = xl_k + i * 4;
                    xst[kk + 0][xl_m] = v.x;
                    xst[kk + 1][xl_m] = v.y;
                    xst[kk + 2][xl_m] = v.z;
                    xst[kk + 3][xl_m] = v.w;
                }
            }
            __syncthreads();
            #pragma unroll 8
            for (int k = 0; k < KC; ++k) {
                float4 wv = *reinterpret_cast<const float4*>(&Wst[k][n0l]);
                float4 xv = *reinterpret_cast<const float4*>(&xst[k][m0]);
                float wa[4] = {wv.x, wv.y, wv.z, wv.w};
                float xa[4] = {xv.x, xv.y, xv.z, xv.w};
                #pragma unroll
                for (int i = 0; i < 4; ++i)
                    #pragma unroll
                    for (int j = 0; j < 4; ++j)
                        acc[i][j] = fmaf(wa[i], xa[j], acc[i][j]);
            }
        }
        // epilogue: one float4 STG per valid m row (unique destination -> no atomics)
        #pragma unroll
        for (int i = 0; i < 4; ++i) {
            float4 o;
            o.x = acc[0][i] + bias.x;
            o.y = acc[1][i] + bias.y;
            o.z = acc[2][i] + bias.z;
            o.w = acc[3][i] + bias.w;
            float* dst = &g_part[slot[i] * 2 + str[i]][tok[i]][N0 + n0l];
            if (val[i]) *reinterpret_cast<float4*>(dst) = o;
        }
    }
}

// ---------------- kernel 3: combine slots + LayerNorm + residual --------
__global__ __launch_bounds__(128) void ln_kernel(
    const float* __restrict__ x_l, const float* __restrict__ x_r,
    const float* __restrict__ lw_l, const float* __restrict__ lb_l,
    const float* __restrict__ lw_r, const float* __restrict__ lb_r,
    float* __restrict__ out)
{
    __shared__ float red[8];
    int bid = blockIdx.x;
    int stream = bid >> 10;            // NTOK = 1024
    int tok = bid & (NTOK - 1);
    int tid = threadIdx.x;

    const float* p0 = g_part[0 * 2 + stream][tok];
    const float* p1 = g_part[1 * 2 + stream][tok];
    const float* xr = (stream ? x_r : x_l) + (size_t)tok * TD;
    const float* w  = stream ? lw_r : lw_l;
    const float* b  = stream ? lb_r : lb_l;

    int base = tid * 4;
    float4 a = *reinterpret_cast<const float4*>(p0 + base);
    float4 c = *reinterpret_cast<const float4*>(p1 + base);
    float v0 = a.x + c.x, v1 = a.y + c.y, v2 = a.z + c.z, v3 = a.w + c.w;
    float s1 = v0 + v1 + v2 + v3;
    float s2 = v0 * v0 + v1 * v1 + v2 * v2 + v3 * v3;
    #pragma unroll
    for (int o = 16; o; o >>= 1) {
        s1 += __shfl_xor_sync(0xffffffffu, s1, o);
        s2 += __shfl_xor_sync(0xffffffffu, s2, o);
    }
    int warp = tid >> 5, lane = tid & 31;
    if (lane == 0) { red[warp] = s1; red[4 + warp] = s2; }
    __syncthreads();
    float S1 = red[0] + red[1] + red[2] + red[3];
    float S2 = red[4] + red[5] + red[6] + red[7];
    float mu  = S1 * (1.f / TD);
    float var = S2 * (1.f / TD) - mu * mu;
    float rs  = rsqrtf(fmaxf(var, 0.f) + 1e-5f);

    float4 wv = *reinterpret_cast<const float4*>(w + base);
    float4 bv = *reinterpret_cast<const float4*>(b + base);
    float4 xv = *reinterpret_cast<const float4*>(xr + base);
    float4 o;
    o.x = (v0 - mu) * rs * wv.x + bv.x + xv.x;
    o.y = (v1 - mu) * rs * wv.y + bv.y + xv.y;
    o.z = (v2 - mu) * rs * wv.z + bv.z + xv.z;
    o.w = (v3 - mu) * rs * wv.w + bv.w + xv.w;
    *reinterpret_cast<float4*>(out + (size_t)stream * NTOK * TD + (size_t)tok * TD + base) = o;
}

// ---------------- launch ----------------
extern "C" void kernel_launch(void* const* d_in, const int* in_sizes, int n_in,
                              void* d_out, int out_size)
{
    const float* x_l   = (const float*)d_in[0];
    const float* x_r   = (const float*)d_in[1];
    const float* cent  = (const float*)d_in[2];
    const float* projW = (const float*)d_in[3];
    const float* projb = (const float*)d_in[4];
    const float* eW    = (const float*)d_in[5];
    const float* eB    = (const float*)d_in[6];
    const float* lwl   = (const float*)d_in[7];
    const float* lbl   = (const float*)d_in[8];
    const float* lwr   = (const float*)d_in[9];
    const float* lbr   = (const float*)d_in[10];
    float* out = (float*)d_out;

    zero_cnt_kernel<<<1, NE>>>();
    router_kernel<<<NTOK, 256>>>(x_l, x_r, cent, projW, projb);
    dim3 g(NE, NT);
    expert_gemm_kernel<<<g, 256>>>(x_l, x_r, eW, eB);
    ln_kernel<<<2 * NTOK, 128>>>(x_l, x_r, lwl, lbl, lwr, lbr, out);
}